// round 6
// baseline (speedup 1.0000x reference)
#include <cuda_runtime.h>

#define NB 64
#define NT 512
#define NI 1024
#define NH 1024
#define NG 4096   // 4*H
#define NBLK 128  // persistent blocks
#define PS 1028   // partial-sum stride per gate-col (floats): %4==0 (float4), %32==4 (banks)

// ---------------- static scratch ----------------
__device__ float g_Wih[NG * NI];                 // gate-interleaved Wih
__device__ float g_bias[NG];                     // bih+bhh, interleaved
__device__ float g_Z[(size_t)NB * NT * NG];      // x-projection + bias (512 MB)
__device__ float g_Hfrag[2 * 128 * 128 * 8];     // [buf][k/8][batch m][pair-perm k%8]
__device__ unsigned g_barcnt;
__device__ volatile unsigned g_barphase;

__device__ __forceinline__ float tf32r(float x) {
    unsigned u;
    asm("cvt.rna.tf32.f32 %0, %1;" : "=r"(u) : "f"(x));
    return __uint_as_float(u);
}
__device__ __forceinline__ unsigned fu(float x) { return __float_as_uint(x); }

__device__ __forceinline__ void mma8(float c[4], const unsigned a[4], const unsigned b[2]) {
    asm volatile(
        "mma.sync.aligned.m16n8k8.row.col.f32.tf32.tf32.f32 "
        "{%0,%1,%2,%3}, {%4,%5,%6,%7}, {%8,%9}, {%0,%1,%2,%3};\n"
        : "+f"(c[0]), "+f"(c[1]), "+f"(c[2]), "+f"(c[3])
        : "r"(a[0]), "r"(a[1]), "r"(a[2]), "r"(a[3]), "r"(b[0]), "r"(b[1]));
}

__device__ __forceinline__ float sigmf_(float x) { return 1.0f / (1.0f + __expf(-x)); }

// ---------------- prep kernels ----------------
__global__ void prep_weights(const float* __restrict__ Wih,
                             const float* __restrict__ bih, const float* __restrict__ bhh) {
    int idx = blockIdx.x * blockDim.x + threadIdx.x;   // < NG*1024
    int n = idx >> 10, k = idx & 1023;
    int j = n >> 2, g = n & 3;
    g_Wih[idx] = Wih[(g * NH + j) * 1024 + k];
    if (k == 0) g_bias[n] = bih[g * NH + j] + bhh[g * NH + j];
}

// h0 -> H_frag[0] in fragment-native layout, tf32-rounded
__global__ void init_state(const float* __restrict__ h0f, const float* __restrict__ h0b) {
    int idx = blockIdx.x * blockDim.x + threadIdx.x;   // < 128*1024
    int m = idx >> 10, j = idx & 1023;
    float h = (m < 64) ? h0f[m * NH + j] : h0b[(m - 64) * NH + j];
    int p = ((j & 3) << 1) | ((j >> 2) & 1);
    g_Hfrag[((size_t)(j >> 3) * 128 + m) * 8 + p] = tf32r(h);
}

__global__ void reset_bar() { g_barcnt = 0; g_barphase = 0; }

// ---------------- phase 1: Z = X @ Wih^T + bias ----------------
__global__ __launch_bounds__(256) void zproj_kernel(const float* __restrict__ X) {
    __shared__ float As[128 * 20];
    __shared__ float Bs2[128 * 20];
    int tid = threadIdx.x;
    int row0 = blockIdx.y * 128;
    int n0 = blockIdx.x * 128;
    const float* Ag = X + (size_t)row0 * NI;
    const float* Bg = g_Wih + (size_t)n0 * NI;

    int lr = tid >> 2;
    int lc = (tid & 3) * 4;
    int w = tid >> 5, lane = tid & 31, gid = lane >> 2, tig = lane & 3;
    int wm = (w >> 2) * 64, wn = (w & 3) * 32;

    float c[4][4][4];
#pragma unroll
    for (int mi = 0; mi < 4; mi++)
#pragma unroll
        for (int ni = 0; ni < 4; ni++)
#pragma unroll
            for (int q = 0; q < 4; q++) c[mi][ni][q] = 0.f;

    float4 pa0 = *(const float4*)(Ag + (size_t)lr * NI + lc);
    float4 pa1 = *(const float4*)(Ag + (size_t)(lr + 64) * NI + lc);
    float4 pb0 = *(const float4*)(Bg + (size_t)lr * NI + lc);
    float4 pb1 = *(const float4*)(Bg + (size_t)(lr + 64) * NI + lc);

    for (int kk = 0; kk < NI; kk += 16) {
        *(float4*)&As[lr * 20 + lc] = make_float4(tf32r(pa0.x), tf32r(pa0.y), tf32r(pa0.z), tf32r(pa0.w));
        *(float4*)&As[(lr + 64) * 20 + lc] = make_float4(tf32r(pa1.x), tf32r(pa1.y), tf32r(pa1.z), tf32r(pa1.w));
        *(float4*)&Bs2[lr * 20 + lc] = make_float4(tf32r(pb0.x), tf32r(pb0.y), tf32r(pb0.z), tf32r(pb0.w));
        *(float4*)&Bs2[(lr + 64) * 20 + lc] = make_float4(tf32r(pb1.x), tf32r(pb1.y), tf32r(pb1.z), tf32r(pb1.w));
        __syncthreads();
        if (kk + 16 < NI) {
            pa0 = *(const float4*)(Ag + (size_t)lr * NI + kk + 16 + lc);
            pa1 = *(const float4*)(Ag + (size_t)(lr + 64) * NI + kk + 16 + lc);
            pb0 = *(const float4*)(Bg + (size_t)lr * NI + kk + 16 + lc);
            pb1 = *(const float4*)(Bg + (size_t)(lr + 64) * NI + kk + 16 + lc);
        }
#pragma unroll
        for (int k8 = 0; k8 < 16; k8 += 8) {
            unsigned a[4][4], b[4][2];
#pragma unroll
            for (int mi = 0; mi < 4; mi++) {
                int rb = wm + mi * 16 + gid;
                a[mi][0] = fu(As[rb * 20 + k8 + tig]);
                a[mi][1] = fu(As[(rb + 8) * 20 + k8 + tig]);
                a[mi][2] = fu(As[rb * 20 + k8 + 4 + tig]);
                a[mi][3] = fu(As[(rb + 8) * 20 + k8 + 4 + tig]);
            }
#pragma unroll
            for (int ni = 0; ni < 4; ni++) {
                int nb = wn + ni * 8 + gid;
                b[ni][0] = fu(Bs2[nb * 20 + k8 + tig]);
                b[ni][1] = fu(Bs2[nb * 20 + k8 + 4 + tig]);
            }
#pragma unroll
            for (int mi = 0; mi < 4; mi++)
#pragma unroll
                for (int ni = 0; ni < 4; ni++) mma8(c[mi][ni], a[mi], b[ni]);
        }
        __syncthreads();
    }

#pragma unroll
    for (int mi = 0; mi < 4; mi++)
#pragma unroll
        for (int ni = 0; ni < 4; ni++) {
            int r = row0 + wm + mi * 16 + gid;
            int col = n0 + wn + ni * 8 + tig * 2;
            float b0 = g_bias[col], b1 = g_bias[col + 1];
            size_t o = (size_t)r * NG + col;
            g_Z[o] = c[mi][ni][0] + b0;
            g_Z[o + 1] = c[mi][ni][1] + b1;
            o += (size_t)8 * NG;
            g_Z[o] = c[mi][ni][2] + b0;
            g_Z[o + 1] = c[mi][ni][3] + b1;
        }
}

// ---------------- grid barrier ----------------
__device__ __forceinline__ void grid_bar(unsigned target) {
    __syncthreads();
    if (threadIdx.x == 0) {
        __threadfence();
        unsigned old = atomicAdd(&g_barcnt, 1u);
        if (old == NBLK - 1) {
            g_barcnt = 0;
            __threadfence();
            g_barphase = target;
        } else {
            while (g_barphase < target) { __nanosleep(40); }
        }
        __threadfence();
    }
    __syncthreads();
}

// ---------------- persistent recurrent kernel (K-split, weights in registers) ----
// Block b: gate cols [32b,32b+32) (hidden units 8b..8b+8).
// Warp w owns K-chunk [128w,128w+128): A-fragments (weights) live in registers,
// loaded once. Per step each warp computes a PARTIAL 32x128 gate tile over its
// K-chunk (B = H fragments straight from L2 via .cg), dumps partials to smem,
// then an epilogue reduces the 8 partials and applies the LSTM pointwise.
__global__ __launch_bounds__(256, 1) void lstm_persistent(float* __restrict__ out,
                                                          const float* __restrict__ Whh,
                                                          const float* __restrict__ c0f,
                                                          const float* __restrict__ c0b) {
    extern __shared__ float part[];   // 32 gate-cols x PS  (part[gc*PS + m*8 + w])

    const int b = blockIdx.x, tid = threadIdx.x;
    const int w = tid >> 5, lane = tid & 31, gid = lane >> 2, tig = lane & 3;

    // ---- one-time: A fragments (gate-permuted Whh rows, tf32) into registers ----
    // a[0]=(r,k) a[1]=(r+8,k) a[2]=(r,k+4) a[3]=(r+8,k+4); k base = (16w+ks)*8+tig
    unsigned Areg[2][16][4];
#pragma unroll
    for (int mt = 0; mt < 2; mt++)
#pragma unroll
        for (int ks = 0; ks < 16; ks++)
#pragma unroll
            for (int q = 0; q < 4; q++) {
                int pr = b * 32 + mt * 16 + gid + 8 * (q & 1);       // gate-interleaved row
                int orow = (pr & 3) * NH + (pr >> 2);                // original Whh row
                int col = (w * 16 + ks) * 8 + tig + 4 * (q >> 1);
                Areg[mt][ks][q] = fu(tf32r(Whh[(size_t)orow * NH + col]));
            }

    // pointwise-thread mapping: item it -> (m = (it*256+tid)>>3, u = (it*256+tid)&7)
    float Creg[4];
#pragma unroll
    for (int it = 0; it < 4; it++) {
        int idx = it * 256 + tid, m = idx >> 3, u = idx & 7, j = b * 8 + u;
        Creg[it] = (m < 64) ? c0f[m * NH + j] : c0b[(m - 64) * NH + j];
    }

    const size_t OB = (size_t)NB * NT * 2048;

    for (int t = 0; t < NT; t++) {
        const float* Hb = g_Hfrag + (size_t)(t & 1) * 131072 + (size_t)w * 16384 + gid * 8 + tig * 2;

        // prefetch Z (streaming; consumed only in the epilogue)
        float4 zreg[4];
#pragma unroll
        for (int it = 0; it < 4; it++) {
            int idx = it * 256 + tid, m = idx >> 3, u = idx & 7;
            size_t zoff = (m < 64) ? ((size_t)m * NT + t) * NG
                                   : ((size_t)(m - 64) * NT + (NT - 1 - t)) * NG;
            zreg[it] = __ldcs((const float4*)&g_Z[zoff + b * 32 + u * 4]);
        }

        // ---- main loop: no LDS, no smem deps; 16 independent LDGs per nt ----
        for (int nt = 0; nt < 16; nt++) {
            float acc[2][4];
#pragma unroll
            for (int mt = 0; mt < 2; mt++)
#pragma unroll
                for (int q = 0; q < 4; q++) acc[mt][q] = 0.f;

#pragma unroll
            for (int ks = 0; ks < 16; ks++) {
                float2 f = __ldcg((const float2*)(Hb + (size_t)ks * 1024 + nt * 64));
                unsigned bb[2] = {fu(f.x), fu(f.y)};
                mma8(acc[0], Areg[0][ks], bb);
                mma8(acc[1], Areg[1][ks], bb);
            }

            // partials -> smem: part[gc*PS + m*8 + w]
#pragma unroll
            for (int mt = 0; mt < 2; mt++) {
                int gc = mt * 16 + gid;
                int mb = nt * 8 + 2 * tig;
                part[gc * PS + mb * 8 + w] = acc[mt][0];
                part[gc * PS + (mb + 1) * 8 + w] = acc[mt][1];
                part[(gc + 8) * PS + mb * 8 + w] = acc[mt][2];
                part[(gc + 8) * PS + (mb + 1) * 8 + w] = acc[mt][3];
            }
        }
        __syncthreads();

        // ---- epilogue: reduce 8 partials, LSTM pointwise ----
        float* Hn = g_Hfrag + (size_t)((t + 1) & 1) * 131072 + (size_t)b * 1024;
#pragma unroll
        for (int it = 0; it < 4; it++) {
            int idx = it * 256 + tid, m = idx >> 3, u = idx & 7, j = b * 8 + u;
            float s[4];
#pragma unroll
            for (int g = 0; g < 4; g++) {
                const float* p = &part[(4 * u + g) * PS + m * 8];
                float4 p0 = *(const float4*)p;
                float4 p1 = *(const float4*)(p + 4);
                s[g] = ((p0.x + p0.y) + (p0.z + p0.w)) + ((p1.x + p1.y) + (p1.z + p1.w));
            }
            float4 z = zreg[it];
            float iv = sigmf_(s[0] + z.x);
            float fv = sigmf_(s[1] + z.y);
            float gv = tanhf(s[2] + z.z);
            float ov = sigmf_(s[3] + z.w);
            float cv = fv * Creg[it] + iv * gv;
            Creg[it] = cv;
            float h = ov * tanhf(cv);
            int p = ((u & 3) << 1) | (u >> 2);
            Hn[m * 8 + p] = tf32r(h);
            if (m < 64) {
                out[((size_t)m * NT + t) * 2048 + j] = h;
                out[((size_t)(63 - m) * NT + t) * 2048 + 1024 + j] = h;
                if (t == NT - 1) out[OB + (size_t)m * 2048 + j] = h;
            } else if (t == NT - 1) {
                out[OB + (size_t)(m - 64) * 2048 + 1024 + j] = h;
            }
        }

        grid_bar((unsigned)(t + 1));   // includes __syncthreads: protects part reuse
    }

    // c_i from registers
#pragma unroll
    for (int it = 0; it < 4; it++) {
        int idx = it * 256 + tid, m = idx >> 3, u = idx & 7, j = b * 8 + u;
        size_t o = OB + 131072 + ((m < 64) ? ((size_t)m * 2048 + j)
                                           : ((size_t)(m - 64) * 2048 + 1024 + j));
        out[o] = Creg[it];
    }
}

extern "C" void kernel_launch(void* const* d_in, const int* in_sizes, int n_in,
                              void* d_out, int out_size) {
    const float* x     = (const float*)d_in[0];
    const float* Wih_f = (const float*)d_in[1];
    const float* Whh_f = (const float*)d_in[2];
    const float* bih_f = (const float*)d_in[3];
    const float* bhh_f = (const float*)d_in[4];
    // d_in[5..8] (_b weights) are unused by the reference computation.
    const float* h0f   = (const float*)d_in[9];
    const float* c0f   = (const float*)d_in[10];
    const float* h0b   = (const float*)d_in[11];
    const float* c0b   = (const float*)d_in[12];
    float* out = (float*)d_out;

    const int smem_bytes = 32 * PS * 4;   // 131584
    cudaFuncSetAttribute(lstm_persistent, cudaFuncAttributeMaxDynamicSharedMemorySize, smem_bytes);

    prep_weights<<<(NG * NI) / 256, 256>>>(Wih_f, bih_f, bhh_f);
    init_state<<<(128 * NH) / 256, 256>>>(h0f, h0b);

    dim3 zg(NG / 128, (NB * NT) / 128);   // (32, 256)
    zproj_kernel<<<zg, 256>>>(x);

    reset_bar<<<1, 1>>>();
    lstm_persistent<<<NBLK, 256, smem_bytes>>>(out, Whh_f, c0f, c0b);
}